// round 7
// baseline (speedup 1.0000x reference)
#include <cuda_runtime.h>
#include <cuda_bf16.h>
#include <math_constants.h>
#include <cstdint>

// Problem constants (fixed by the dataset)
#define NN   50000
#define EE   800000
#define E2   (EE + NN)      // edges + self loops = 850000
#define FIN  512
#define H1   8
#define C1   32
#define D1   (H1 * C1)      // 256
#define CLS  40

// ---------------- scratch (static device globals; no runtime alloc) ----------
__device__ float g_h1[NN * D1];          // layer1 linear output [N,256]
__device__ float g_as1[NN * H1];
__device__ float g_ad1[NN * H1];
__device__ float g_hout1[NN * D1];       // elu(agg1 + b1) [N,256]
__device__ float g_h2lin[NN * CLS];
__device__ float g_as2[NN];
__device__ float g_ad2[NN];
__device__ float g_wbuf[H1 * E2];        // per-head planes: [h][edge]
__device__ float g_wbuf2[E2];
__device__ int   g_deg[NN];
__device__ int   g_incl[NN];
__device__ int   g_starts[NN];
__device__ int   g_cursor[NN];
__device__ int   g_ssrc[E2];
__device__ int   g_parts[64];
__device__ int   g_parts_ex[64];
// bf16 split-precision operands for GEMM1
__device__ uint32_t g_xhi[NN * (FIN / 2)];      // bf16 pairs per row
__device__ uint32_t g_xlo[NN * (FIN / 2)];
__device__ uint32_t g_w1t_hi[D1 * (FIN / 2)];   // W1 transposed: [n][kp]
__device__ uint32_t g_w1t_lo[D1 * (FIN / 2)];

// ---------------- bf16 split helpers -----------------------------------------
__device__ __forceinline__ void split2(float x, float y, uint32_t& hi, uint32_t& lo) {
    __nv_bfloat16 hx = __float2bfloat16_rn(x);
    __nv_bfloat16 hy = __float2bfloat16_rn(y);
    float lxf = x - __bfloat162float(hx);
    float lyf = y - __bfloat162float(hy);
    __nv_bfloat162 hv; hv.x = hx; hv.y = hy;
    __nv_bfloat162 lv = __floats2bfloat162_rn(lxf, lyf);
    hi = *reinterpret_cast<uint32_t*>(&hv);
    lo = *reinterpret_cast<uint32_t*>(&lv);
}

__global__ void prep_x_kernel(const float* __restrict__ x) {
    int i = blockIdx.x * blockDim.x + threadIdx.x;
    const int NQ = NN * FIN / 4;
    if (i >= NQ) return;
    float4 v = ((const float4*)x)[i];
    uint32_t h0, l0, h1, l1;
    split2(v.x, v.y, h0, l0);
    split2(v.z, v.w, h1, l1);
    g_xhi[2 * i]     = h0;  g_xhi[2 * i + 1] = h1;
    g_xlo[2 * i]     = l0;  g_xlo[2 * i + 1] = l1;
}

__global__ void prep_w_kernel(const float* __restrict__ W1) {
    int idx = blockIdx.x * blockDim.x + threadIdx.x;
    if (idx >= D1 * (FIN / 2)) return;
    int n = idx >> 8;
    int kp = idx & 255;
    float a = W1[(size_t)(2 * kp) * D1 + n];
    float b = W1[(size_t)(2 * kp + 1) * D1 + n];
    uint32_t hi, lo;
    split2(a, b, hi, lo);
    g_w1t_hi[idx] = hi;
    g_w1t_lo[idx] = lo;
}

// ---------------- tensor-core GEMM1 + fused alpha1 ----------------------------
// CTA: 128 threads (4 warps), tile 128x128, warp tile 64x64 (2x2 warp grid).
#define MMA_BF16(c, a0, a1, a2, a3, b0, b1)                                    \
    asm volatile(                                                              \
        "mma.sync.aligned.m16n8k16.row.col.f32.bf16.bf16.f32 "                 \
        "{%0,%1,%2,%3}, {%4,%5,%6,%7}, {%8,%9}, {%0,%1,%2,%3};\n"              \
        : "+f"(c[0]), "+f"(c[1]), "+f"(c[2]), "+f"(c[3])                       \
        : "r"(a0), "r"(a1), "r"(a2), "r"(a3), "r"(b0), "r"(b1))

__device__ __forceinline__ void ldm4(uint32_t* r, uint32_t saddr) {
    asm volatile("ldmatrix.sync.aligned.m8n8.x4.shared.b16 {%0,%1,%2,%3}, [%4];"
                 : "=r"(r[0]), "=r"(r[1]), "=r"(r[2]), "=r"(r[3]) : "r"(saddr));
}

__global__ void __launch_bounds__(128, 2) sgemm1_tc_kernel(const float* __restrict__ a_src1,
                                                           const float* __restrict__ a_dst1) {
    __shared__ uint32_t As_hi[2][128 * 8];
    __shared__ uint32_t As_lo[2][128 * 8];
    __shared__ uint32_t Bs_hi[2][128 * 8];
    __shared__ uint32_t Bs_lo[2][128 * 8];

    const int t = threadIdx.x, lane = t & 31, wid = t >> 5;
    const int warpM = wid >> 1, warpN = wid & 1;
    const int rowBase = blockIdx.y * 128, colBase = blockIdx.x * 128;

    // global load mapping: thread t loads full row t (8 uint32 = 2 uint4) per array
    const int row = t;
    const int arow_g = rowBase + row;
    const bool avalid = arow_g < NN;
    const size_t a_base = (size_t)(avalid ? arow_g : 0) * (FIN / 2);
    const size_t b_base = (size_t)(colBase + row) * (FIN / 2);
    const int s0 = row * 8 + (0 ^ (row & 4));
    const int s1 = row * 8 + (4 ^ (row & 4));

    // ldmatrix per-lane byte offsets
    const int lr = lane & 15, kq = lane >> 4;
    uint32_t off_a[4], off_b[4];
#pragma unroll
    for (int mt = 0; mt < 4; mt++) {
        int r = warpM * 64 + mt * 16 + lr;
        off_a[mt] = (uint32_t)(r * 8 + ((kq * 4) ^ (r & 4))) * 4u;
    }
#pragma unroll
    for (int np = 0; np < 4; np++) {
        int r = warpN * 64 + np * 16 + lr;
        off_b[np] = (uint32_t)(r * 8 + ((kq * 4) ^ (r & 4))) * 4u;
    }
    uint32_t baseAh[2], baseAl[2], baseBh[2], baseBl[2];
#pragma unroll
    for (int b = 0; b < 2; b++) {
        baseAh[b] = (uint32_t)__cvta_generic_to_shared(&As_hi[b][0]);
        baseAl[b] = (uint32_t)__cvta_generic_to_shared(&As_lo[b][0]);
        baseBh[b] = (uint32_t)__cvta_generic_to_shared(&Bs_hi[b][0]);
        baseBl[b] = (uint32_t)__cvta_generic_to_shared(&Bs_lo[b][0]);
    }

    float acc[4][8][4];
#pragma unroll
    for (int mt = 0; mt < 4; mt++)
#pragma unroll
        for (int nt = 0; nt < 8; nt++)
#pragma unroll
            for (int q = 0; q < 4; q++) acc[mt][nt][q] = 0.f;

    const uint4 z4 = make_uint4(0, 0, 0, 0);
    uint4 rah0, rah1, ral0, ral1, rbh0, rbh1, rbl0, rbl1;

    // prologue: stage 0
    rah0 = avalid ? *(const uint4*)&g_xhi[a_base + 0] : z4;
    rah1 = avalid ? *(const uint4*)&g_xhi[a_base + 4] : z4;
    ral0 = avalid ? *(const uint4*)&g_xlo[a_base + 0] : z4;
    ral1 = avalid ? *(const uint4*)&g_xlo[a_base + 4] : z4;
    rbh0 = *(const uint4*)&g_w1t_hi[b_base + 0];
    rbh1 = *(const uint4*)&g_w1t_hi[b_base + 4];
    rbl0 = *(const uint4*)&g_w1t_lo[b_base + 0];
    rbl1 = *(const uint4*)&g_w1t_lo[b_base + 4];
    *(uint4*)&As_hi[0][s0] = rah0;  *(uint4*)&As_hi[0][s1] = rah1;
    *(uint4*)&As_lo[0][s0] = ral0;  *(uint4*)&As_lo[0][s1] = ral1;
    *(uint4*)&Bs_hi[0][s0] = rbh0;  *(uint4*)&Bs_hi[0][s1] = rbh1;
    *(uint4*)&Bs_lo[0][s0] = rbl0;  *(uint4*)&Bs_lo[0][s1] = rbl1;
    __syncthreads();

    const int NSTAGE = FIN / 16;    // 32
    for (int ks = 0; ks < NSTAGE; ks++) {
        const int cur = ks & 1;
        if (ks + 1 < NSTAGE) {
            size_t off = (size_t)(ks + 1) * 8;
            rah0 = avalid ? *(const uint4*)&g_xhi[a_base + off]     : z4;
            rah1 = avalid ? *(const uint4*)&g_xhi[a_base + off + 4] : z4;
            ral0 = avalid ? *(const uint4*)&g_xlo[a_base + off]     : z4;
            ral1 = avalid ? *(const uint4*)&g_xlo[a_base + off + 4] : z4;
            rbh0 = *(const uint4*)&g_w1t_hi[b_base + off];
            rbh1 = *(const uint4*)&g_w1t_hi[b_base + off + 4];
            rbl0 = *(const uint4*)&g_w1t_lo[b_base + off];
            rbl1 = *(const uint4*)&g_w1t_lo[b_base + off + 4];
        }

        uint32_t afh[4][4], afl[4][4];
#pragma unroll
        for (int mt = 0; mt < 4; mt++) {
            ldm4(afh[mt], baseAh[cur] + off_a[mt]);
            ldm4(afl[mt], baseAl[cur] + off_a[mt]);
        }
#pragma unroll
        for (int np = 0; np < 4; np++) {
            uint32_t bh[4], bl[4];
            ldm4(bh, baseBh[cur] + off_b[np]);
            ldm4(bl, baseBl[cur] + off_b[np]);
#pragma unroll
            for (int mt = 0; mt < 4; mt++) {
                MMA_BF16(acc[mt][2 * np],     afh[mt][0], afh[mt][1], afh[mt][2], afh[mt][3], bh[0], bh[2]);
                MMA_BF16(acc[mt][2 * np],     afh[mt][0], afh[mt][1], afh[mt][2], afh[mt][3], bl[0], bl[2]);
                MMA_BF16(acc[mt][2 * np],     afl[mt][0], afl[mt][1], afl[mt][2], afl[mt][3], bh[0], bh[2]);
                MMA_BF16(acc[mt][2 * np + 1], afh[mt][0], afh[mt][1], afh[mt][2], afh[mt][3], bh[1], bh[3]);
                MMA_BF16(acc[mt][2 * np + 1], afh[mt][0], afh[mt][1], afh[mt][2], afh[mt][3], bl[1], bl[3]);
                MMA_BF16(acc[mt][2 * np + 1], afl[mt][0], afl[mt][1], afl[mt][2], afl[mt][3], bh[1], bh[3]);
            }
        }
        if (ks + 1 < NSTAGE) {
            const int nxt = 1 - cur;
            *(uint4*)&As_hi[nxt][s0] = rah0;  *(uint4*)&As_hi[nxt][s1] = rah1;
            *(uint4*)&As_lo[nxt][s0] = ral0;  *(uint4*)&As_lo[nxt][s1] = ral1;
            *(uint4*)&Bs_hi[nxt][s0] = rbh0;  *(uint4*)&Bs_hi[nxt][s1] = rbh1;
            *(uint4*)&Bs_lo[nxt][s0] = rbl0;  *(uint4*)&Bs_lo[nxt][s1] = rbl1;
            __syncthreads();
        }
    }

    // ---- epilogue: store h1 + fused alpha1 for this CTA's 4 heads -----------
#pragma unroll
    for (int mt = 0; mt < 4; mt++) {
        const int r0 = rowBase + warpM * 64 + mt * 16 + (lane >> 2);
        const int r1 = r0 + 8;
        // h1 stores
#pragma unroll
        for (int nt = 0; nt < 8; nt++) {
            const int c = colBase + warpN * 64 + nt * 8 + (lane & 3) * 2;
            if (r0 < NN) *(float2*)&g_h1[(size_t)r0 * D1 + c] = make_float2(acc[mt][nt][0], acc[mt][nt][1]);
            if (r1 < NN) *(float2*)&g_h1[(size_t)r1 * D1 + c] = make_float2(acc[mt][nt][2], acc[mt][nt][3]);
        }
        // alpha partials: 2 heads per warp (head = 4 consecutive nt tiles)
#pragma unroll
        for (int hl = 0; hl < 2; hl++) {
            float ps0 = 0.f, pd0 = 0.f, ps1 = 0.f, pd1 = 0.f;
#pragma unroll
            for (int ntq = 0; ntq < 4; ntq++) {
                const int nt = hl * 4 + ntq;
                const int c = colBase + warpN * 64 + nt * 8 + (lane & 3) * 2;
                float av0 = __ldg(&a_src1[c]), av1 = __ldg(&a_src1[c + 1]);
                float dv0 = __ldg(&a_dst1[c]), dv1 = __ldg(&a_dst1[c + 1]);
                ps0 += acc[mt][nt][0] * av0 + acc[mt][nt][1] * av1;
                pd0 += acc[mt][nt][0] * dv0 + acc[mt][nt][1] * dv1;
                ps1 += acc[mt][nt][2] * av0 + acc[mt][nt][3] * av1;
                pd1 += acc[mt][nt][2] * dv0 + acc[mt][nt][3] * dv1;
            }
            // quad reduction (cols within the head)
#pragma unroll
            for (int off = 1; off < 4; off <<= 1) {
                ps0 += __shfl_xor_sync(0xffffffffu, ps0, off);
                pd0 += __shfl_xor_sync(0xffffffffu, pd0, off);
                ps1 += __shfl_xor_sync(0xffffffffu, ps1, off);
                pd1 += __shfl_xor_sync(0xffffffffu, pd1, off);
            }
            if ((lane & 3) == 0) {
                const int hg = (colBase >> 5) + warpN * 2 + hl;
                if (r0 < NN) { g_as1[r0 * H1 + hg] = ps0; g_ad1[r0 * H1 + hg] = pd0; }
                if (r1 < NN) { g_as1[r1 * H1 + hg] = ps1; g_ad1[r1 * H1 + hg] = pd1; }
            }
        }
    }
}

// ---------------- CSR build ---------------------------------------------------
__global__ void zero_deg_kernel() {
    int i = blockIdx.x * blockDim.x + threadIdx.x;
    if (i < NN) g_deg[i] = 0;
}

__global__ void hist_kernel(const int* __restrict__ ei) {
    int i = blockIdx.x * blockDim.x + threadIdx.x;
    if (i >= E2) return;
    int d = (i < EE) ? __ldg(&ei[EE + i]) : (i - EE);
    atomicAdd(&g_deg[d], 1);
}

__global__ void scan_block_kernel() {
    __shared__ int sh[1024];
    int tid = threadIdx.x;
    int i = blockIdx.x * 1024 + tid;
    int v = (i < NN) ? g_deg[i] : 0;
    sh[tid] = v;
    __syncthreads();
#pragma unroll
    for (int off = 1; off < 1024; off <<= 1) {
        int t = (tid >= off) ? sh[tid - off] : 0;
        __syncthreads();
        sh[tid] += t;
        __syncthreads();
    }
    if (i < NN) g_incl[i] = sh[tid];
    if (tid == 1023) g_parts[blockIdx.x] = sh[tid];
}

__global__ void scan_parts_kernel(int nb) {
    __shared__ int sh[64];
    int tid = threadIdx.x;
    int v = (tid < nb) ? g_parts[tid] : 0;
    sh[tid] = v;
    __syncthreads();
#pragma unroll
    for (int off = 1; off < 64; off <<= 1) {
        int t = (tid >= off) ? sh[tid - off] : 0;
        __syncthreads();
        sh[tid] += t;
        __syncthreads();
    }
    if (tid < nb) g_parts_ex[tid] = sh[tid] - v;
}

__global__ void finalize_scan_kernel() {
    int i = blockIdx.x * blockDim.x + threadIdx.x;
    if (i >= NN) return;
    int start = g_incl[i] - g_deg[i] + g_parts_ex[i >> 10];
    g_starts[i] = start;
    g_cursor[i] = start;
}

__global__ void fill_kernel(const int* __restrict__ ei) {
    int i = blockIdx.x * blockDim.x + threadIdx.x;
    if (i >= E2) return;
    int s, d;
    if (i < EE) { s = __ldg(&ei[i]); d = __ldg(&ei[EE + i]); }
    else        { s = i - EE; d = s; }
    int p = atomicAdd(&g_cursor[d], 1);
    g_ssrc[p] = s;
}

// ---------------- layer1 aggregation (warp per node*head) ---------------------
__global__ void agg1_kernel(const float* __restrict__ b1) {
    int gw = (blockIdx.x * blockDim.x + threadIdx.x) >> 5;
    int lane = threadIdx.x & 31;
    int n = gw >> 3;                 // node
    int h = gw & 7;                  // head
    if (n >= NN) return;
    int st = g_starts[n];
    int d  = g_deg[n];

    float adh = g_ad1[n * H1 + h];
    float* wplane = &g_wbuf[(size_t)h * E2];

    // pass A: exp per edge (coalesced plane write) + denominator
    float den = 0.f;
    for (int j = lane; j < d; j += 32) {
        int s = __ldg(&g_ssrc[st + j]);
        float e = __ldg(&g_as1[s * H1 + h]) + adh;
        e = fmaxf(e, 0.2f * e);
        float ex = __expf(e);
        wplane[st + j] = ex;
        den += ex;
    }
#pragma unroll
    for (int off = 16; off > 0; off >>= 1)
        den += __shfl_xor_sync(0xffffffffu, den, off);
    float inv = 1.f / (den + 1e-16f);

    // pass B: one aligned 128B line per edge
    float a0 = 0.f;
#pragma unroll 8
    for (int j = 0; j < d; j++) {
        int s = __ldg(&g_ssrc[st + j]);
        float w = wplane[st + j] * inv;
        a0 = fmaf(__ldg(&g_h1[(size_t)s * D1 + h * 32 + lane]), w, a0);
    }

    float v = a0 + __ldg(&b1[h * 32 + lane]);
    v = (v > 0.f) ? v : expm1f(v);
    g_hout1[(size_t)n * D1 + h * 32 + lane] = v;
}

// ---------------- layer2 linear + alpha2 --------------------------------------
__global__ void layer2_linear_kernel(const float* __restrict__ W2,
                                     const float* __restrict__ a_src2,
                                     const float* __restrict__ a_dst2) {
    __shared__ float Ws[D1 * CLS + 64];
    __shared__ float as_sh[CLS], ad_sh[CLS];
    int tid = threadIdx.x;
    for (int i = tid; i < D1 * CLS + 64; i += blockDim.x)
        Ws[i] = (i < D1 * CLS) ? W2[i] : 0.f;
    if (tid < CLS) { as_sh[tid] = a_src2[tid]; ad_sh[tid] = a_dst2[tid]; }
    __syncthreads();

    int lane = tid & 31;
    int warpsPerBlock = blockDim.x >> 5;
    int gw = blockIdx.x * warpsPerBlock + (tid >> 5);
    int stride = gridDim.x * warpsPerBlock;

    for (int n = gw; n < NN; n += stride) {
        const float* xp = &g_hout1[(size_t)n * D1];
        float acc0a = 0.f, acc0b = 0.f, acc1a = 0.f, acc1b = 0.f;
#pragma unroll
        for (int kb = 0; kb < D1 / 32; kb++) {
            float xv = xp[kb * 32 + lane];
#pragma unroll
            for (int j = 0; j < 32; j += 2) {
                float xj0 = __shfl_sync(0xffffffffu, xv, j);
                float xj1 = __shfl_sync(0xffffffffu, xv, j + 1);
                int k0 = kb * 32 + j;
                acc0a = fmaf(xj0, Ws[k0 * CLS + lane], acc0a);
                acc1a = fmaf(xj0, Ws[k0 * CLS + 32 + lane], acc1a);
                acc0b = fmaf(xj1, Ws[(k0 + 1) * CLS + lane], acc0b);
                acc1b = fmaf(xj1, Ws[(k0 + 1) * CLS + 32 + lane], acc1b);
            }
        }
        float v0 = acc0a + acc0b;
        float v1 = acc1a + acc1b;
        g_h2lin[(size_t)n * CLS + lane] = v0;
        if (lane < CLS - 32) g_h2lin[(size_t)n * CLS + 32 + lane] = v1;
        float ps = v0 * as_sh[lane] + ((lane < CLS - 32) ? v1 * as_sh[32 + lane] : 0.f);
        float pd = v0 * ad_sh[lane] + ((lane < CLS - 32) ? v1 * ad_sh[32 + lane] : 0.f);
#pragma unroll
        for (int off = 16; off > 0; off >>= 1) {
            ps += __shfl_xor_sync(0xffffffffu, ps, off);
            pd += __shfl_xor_sync(0xffffffffu, pd, off);
        }
        if (lane == 0) { g_as2[n] = ps; g_ad2[n] = pd; }
    }
}

// ---------------- layer2 aggregation + log_softmax ----------------------------
__global__ void agg2_kernel(const float* __restrict__ b2, float* __restrict__ out) {
    int n = (blockIdx.x * blockDim.x + threadIdx.x) >> 5;
    int lane = threadIdx.x & 31;
    if (n >= NN) return;
    int st = g_starts[n];
    int d  = g_deg[n];
    float adn = g_ad2[n];

    float den = 0.f;
    for (int j = lane; j < d; j += 32) {
        int s = __ldg(&g_ssrc[st + j]);
        float e = __ldg(&g_as2[s]) + adn;
        e = fmaxf(e, 0.2f * e);
        float ex = __expf(e);
        g_wbuf2[st + j] = ex;
        den += ex;
    }
#pragma unroll
    for (int off = 16; off > 0; off >>= 1)
        den += __shfl_xor_sync(0xffffffffu, den, off);
    float inv = 1.f / (den + 1e-16f);

    float acc0 = 0.f, acc1 = 0.f;
#pragma unroll 4
    for (int j = 0; j < d; j++) {
        int s = __ldg(&g_ssrc[st + j]);
        float w = g_wbuf2[st + j] * inv;
        const float* hp = &g_h2lin[(size_t)s * CLS];
        acc0 = fmaf(__ldg(&hp[lane]), w, acc0);
        if (lane < CLS - 32) acc1 = fmaf(__ldg(&hp[32 + lane]), w, acc1);
    }
    float v0 = acc0 + __ldg(&b2[lane]);
    float v1 = (lane < CLS - 32) ? (acc1 + __ldg(&b2[32 + lane])) : -CUDART_INF_F;

    float m = fmaxf(v0, v1);
#pragma unroll
    for (int off = 16; off > 0; off >>= 1)
        m = fmaxf(m, __shfl_xor_sync(0xffffffffu, m, off));
    float s0 = __expf(v0 - m) + ((lane < CLS - 32) ? __expf(v1 - m) : 0.f);
#pragma unroll
    for (int off = 16; off > 0; off >>= 1)
        s0 += __shfl_xor_sync(0xffffffffu, s0, off);
    float lse = m + logf(s0);

    out[(size_t)n * CLS + lane] = v0 - lse;
    if (lane < CLS - 32) out[(size_t)n * CLS + 32 + lane] = v1 - lse;
}

// ---------------- launch ------------------------------------------------------
extern "C" void kernel_launch(void* const* d_in, const int* in_sizes, int n_in,
                              void* d_out, int out_size) {
    const float* x      = (const float*)d_in[0];
    const int*   ei     = (const int*)d_in[1];
    const float* W1     = (const float*)d_in[2];
    const float* a_src1 = (const float*)d_in[3];
    const float* a_dst1 = (const float*)d_in[4];
    const float* b1     = (const float*)d_in[5];
    const float* W2     = (const float*)d_in[6];
    const float* a_src2 = (const float*)d_in[7];
    const float* a_dst2 = (const float*)d_in[8];
    const float* b2     = (const float*)d_in[9];
    float* out = (float*)d_out;

    const int nb_scan = (NN + 1023) / 1024;   // 49

    // prep, then GEMM at launch slot 4 (ncu capture window)
    prep_x_kernel<<<(NN * FIN / 4 + 255) / 256, 256>>>(x);
    prep_w_kernel<<<(D1 * (FIN / 2) + 255) / 256, 256>>>(W1);
    zero_deg_kernel<<<(NN + 255) / 256, 256>>>();
    sgemm1_tc_kernel<<<dim3(2, (NN + 127) / 128), 128>>>(a_src1, a_dst1);

    // CSR build chain
    hist_kernel<<<(E2 + 255) / 256, 256>>>(ei);
    scan_block_kernel<<<nb_scan, 1024>>>();
    scan_parts_kernel<<<1, 64>>>(nb_scan);
    finalize_scan_kernel<<<(NN + 255) / 256, 256>>>();
    fill_kernel<<<(E2 + 255) / 256, 256>>>(ei);

    // layer 1 aggregation (alpha1 now fused into GEMM epilogue)
    agg1_kernel<<<((size_t)NN * 8 * 32 + 255) / 256, 256>>>(b1);

    // layer 2
    layer2_linear_kernel<<<592, 256>>>(W2, a_src2, a_dst2);
    agg2_kernel<<<(NN * 32 + 255) / 256, 256>>>(b2, out);
}

// round 8
// speedup vs baseline: 1.1106x; 1.1106x over previous
#include <cuda_runtime.h>
#include <cuda_bf16.h>
#include <math_constants.h>
#include <cstdint>

// Problem constants (fixed by the dataset)
#define NN   50000
#define EE   800000
#define E2   (EE + NN)      // edges + self loops = 850000
#define FIN  512
#define H1   8
#define C1   32
#define D1   (H1 * C1)      // 256
#define CLS  40

// ---------------- scratch (static device globals; no runtime alloc) ----------
__device__ float g_h1[NN * D1];          // layer1 linear output [N,256]
__device__ float g_as1[NN * H1];
__device__ float g_ad1[NN * H1];
__device__ float g_hout1[NN * D1];       // elu(agg1 + b1) [N,256]
__device__ float g_h2lin[NN * CLS];
__device__ float g_as2[NN];
__device__ float g_ad2[NN];
__device__ float g_wbuf[H1 * E2];        // per-head planes: [h][edge]
__device__ float g_wbuf2[E2];
__device__ int   g_deg[NN];
__device__ int   g_incl[NN];
__device__ int   g_starts[NN];
__device__ int   g_cursor[NN];
__device__ int   g_ssrc[E2];
__device__ int   g_parts[64];
__device__ int   g_parts_ex[64];
// bf16 split-precision operands for GEMM1
__device__ uint32_t g_xhi[NN * (FIN / 2)];      // bf16 pairs per row
__device__ uint32_t g_xlo[NN * (FIN / 2)];
__device__ uint32_t g_w1t_hi[D1 * (FIN / 2)];   // W1 transposed: [n][kp]
__device__ uint32_t g_w1t_lo[D1 * (FIN / 2)];

// ---------------- bf16 split helpers -----------------------------------------
__device__ __forceinline__ void split2(float x, float y, uint32_t& hi, uint32_t& lo) {
    __nv_bfloat16 hx = __float2bfloat16_rn(x);
    __nv_bfloat16 hy = __float2bfloat16_rn(y);
    float lxf = x - __bfloat162float(hx);
    float lyf = y - __bfloat162float(hy);
    __nv_bfloat162 hv; hv.x = hx; hv.y = hy;
    __nv_bfloat162 lv = __floats2bfloat162_rn(lxf, lyf);
    hi = *reinterpret_cast<uint32_t*>(&hv);
    lo = *reinterpret_cast<uint32_t*>(&lv);
}

__global__ void prep_x_kernel(const float* __restrict__ x) {
    int i = blockIdx.x * blockDim.x + threadIdx.x;
    const int NQ = NN * FIN / 4;
    if (i >= NQ) return;
    float4 v = ((const float4*)x)[i];
    uint32_t h0, l0, h1, l1;
    split2(v.x, v.y, h0, l0);
    split2(v.z, v.w, h1, l1);
    g_xhi[2 * i]     = h0;  g_xhi[2 * i + 1] = h1;
    g_xlo[2 * i]     = l0;  g_xlo[2 * i + 1] = l1;
}

__global__ void prep_w_kernel(const float* __restrict__ W1) {
    int idx = blockIdx.x * blockDim.x + threadIdx.x;
    if (idx >= D1 * (FIN / 2)) return;
    int n = idx >> 8;
    int kp = idx & 255;
    float a = W1[(size_t)(2 * kp) * D1 + n];
    float b = W1[(size_t)(2 * kp + 1) * D1 + n];
    uint32_t hi, lo;
    split2(a, b, hi, lo);
    g_w1t_hi[idx] = hi;
    g_w1t_lo[idx] = lo;
}

// ---------------- tensor-core GEMM1 + fused alpha1 ----------------------------
// R5 config: 256 threads, 8 warps (4M x 2N), warp tile 32x64, 2 CTAs/SM.
#define MMA_BF16(c, a0, a1, a2, a3, b0, b1)                                    \
    asm volatile(                                                              \
        "mma.sync.aligned.m16n8k16.row.col.f32.bf16.bf16.f32 "                 \
        "{%0,%1,%2,%3}, {%4,%5,%6,%7}, {%8,%9}, {%0,%1,%2,%3};\n"              \
        : "+f"(c[0]), "+f"(c[1]), "+f"(c[2]), "+f"(c[3])                       \
        : "r"(a0), "r"(a1), "r"(a2), "r"(a3), "r"(b0), "r"(b1))

__device__ __forceinline__ void ldm4(uint32_t* r, uint32_t saddr) {
    asm volatile("ldmatrix.sync.aligned.m8n8.x4.shared.b16 {%0,%1,%2,%3}, [%4];"
                 : "=r"(r[0]), "=r"(r[1]), "=r"(r[2]), "=r"(r[3]) : "r"(saddr));
}

__global__ void __launch_bounds__(256, 2) sgemm1_tc_kernel(const float* __restrict__ a_src1,
                                                           const float* __restrict__ a_dst1) {
    __shared__ uint32_t As_hi[2][128 * 8];
    __shared__ uint32_t As_lo[2][128 * 8];
    __shared__ uint32_t Bs_hi[2][128 * 8];
    __shared__ uint32_t Bs_lo[2][128 * 8];

    const int t = threadIdx.x, lane = t & 31, wid = t >> 5;
    const int warpM = wid >> 1, warpN = wid & 1;
    const int rowBase = blockIdx.y * 128, colBase = blockIdx.x * 128;

    // global load mapping: thread covers one row-half (4 uint32 = 8 k)
    const int lrow  = t >> 1;
    const int lhalf = t & 1;
    const int arow_g = rowBase + lrow;
    const bool avalid = arow_g < NN;
    const size_t a_base = (size_t)(avalid ? arow_g : 0) * (FIN / 2) + lhalf * 4;
    const size_t b_base = (size_t)(colBase + lrow) * (FIN / 2) + lhalf * 4;
    const int s_off = lrow * 8 + ((lhalf * 4) ^ (lrow & 4));   // swizzled write idx

    // ldmatrix per-lane byte offsets
    const int lr = lane & 15, kq = lane >> 4;
    uint32_t off_a[2], off_b[4];
#pragma unroll
    for (int mt = 0; mt < 2; mt++) {
        int r = warpM * 32 + mt * 16 + lr;
        off_a[mt] = (uint32_t)(r * 8 + ((kq * 4) ^ (r & 4))) * 4u;
    }
#pragma unroll
    for (int np = 0; np < 4; np++) {
        int r = warpN * 64 + np * 16 + lr;
        off_b[np] = (uint32_t)(r * 8 + ((kq * 4) ^ (r & 4))) * 4u;
    }
    uint32_t baseAh[2], baseAl[2], baseBh[2], baseBl[2];
#pragma unroll
    for (int b = 0; b < 2; b++) {
        baseAh[b] = (uint32_t)__cvta_generic_to_shared(&As_hi[b][0]);
        baseAl[b] = (uint32_t)__cvta_generic_to_shared(&As_lo[b][0]);
        baseBh[b] = (uint32_t)__cvta_generic_to_shared(&Bs_hi[b][0]);
        baseBl[b] = (uint32_t)__cvta_generic_to_shared(&Bs_lo[b][0]);
    }

    float acc[2][8][4];
#pragma unroll
    for (int mt = 0; mt < 2; mt++)
#pragma unroll
        for (int nt = 0; nt < 8; nt++)
#pragma unroll
            for (int q = 0; q < 4; q++) acc[mt][nt][q] = 0.f;

    const uint4 z4 = make_uint4(0, 0, 0, 0);
    uint4 ra_h, ra_l, rb_h, rb_l;

    ra_h = avalid ? *(const uint4*)&g_xhi[a_base] : z4;
    ra_l = avalid ? *(const uint4*)&g_xlo[a_base] : z4;
    rb_h = *(const uint4*)&g_w1t_hi[b_base];
    rb_l = *(const uint4*)&g_w1t_lo[b_base];
    *(uint4*)&As_hi[0][s_off] = ra_h;
    *(uint4*)&As_lo[0][s_off] = ra_l;
    *(uint4*)&Bs_hi[0][s_off] = rb_h;
    *(uint4*)&Bs_lo[0][s_off] = rb_l;
    __syncthreads();

    const int NSTAGE = FIN / 16;    // 32
    for (int ks = 0; ks < NSTAGE; ks++) {
        const int cur = ks & 1;
        if (ks + 1 < NSTAGE) {
            size_t off = (size_t)(ks + 1) * 8;
            ra_h = avalid ? *(const uint4*)&g_xhi[a_base + off] : z4;
            ra_l = avalid ? *(const uint4*)&g_xlo[a_base + off] : z4;
            rb_h = *(const uint4*)&g_w1t_hi[b_base + off];
            rb_l = *(const uint4*)&g_w1t_lo[b_base + off];
        }

        uint32_t afh[2][4], afl[2][4];
        ldm4(afh[0], baseAh[cur] + off_a[0]);
        ldm4(afh[1], baseAh[cur] + off_a[1]);
        ldm4(afl[0], baseAl[cur] + off_a[0]);
        ldm4(afl[1], baseAl[cur] + off_a[1]);

#pragma unroll
        for (int np = 0; np < 4; np++) {
            uint32_t bh[4], bl[4];
            ldm4(bh, baseBh[cur] + off_b[np]);
            ldm4(bl, baseBl[cur] + off_b[np]);
#pragma unroll
            for (int mt = 0; mt < 2; mt++) {
                MMA_BF16(acc[mt][2 * np],     afh[mt][0], afh[mt][1], afh[mt][2], afh[mt][3], bh[0], bh[2]);
                MMA_BF16(acc[mt][2 * np],     afh[mt][0], afh[mt][1], afh[mt][2], afh[mt][3], bl[0], bl[2]);
                MMA_BF16(acc[mt][2 * np],     afl[mt][0], afl[mt][1], afl[mt][2], afl[mt][3], bh[0], bh[2]);
                MMA_BF16(acc[mt][2 * np + 1], afh[mt][0], afh[mt][1], afh[mt][2], afh[mt][3], bh[1], bh[3]);
                MMA_BF16(acc[mt][2 * np + 1], afh[mt][0], afh[mt][1], afh[mt][2], afh[mt][3], bl[1], bl[3]);
                MMA_BF16(acc[mt][2 * np + 1], afl[mt][0], afl[mt][1], afl[mt][2], afl[mt][3], bh[1], bh[3]);
            }
        }
        if (ks + 1 < NSTAGE) {
            const int nxt = 1 - cur;
            *(uint4*)&As_hi[nxt][s_off] = ra_h;
            *(uint4*)&As_lo[nxt][s_off] = ra_l;
            *(uint4*)&Bs_hi[nxt][s_off] = rb_h;
            *(uint4*)&Bs_lo[nxt][s_off] = rb_l;
            __syncthreads();
        }
    }

    // ---- epilogue: store h1 + fused alpha1 (2 heads per warp) ----------------
#pragma unroll
    for (int mt = 0; mt < 2; mt++) {
        const int r0 = rowBase + warpM * 32 + mt * 16 + (lane >> 2);
        const int r1 = r0 + 8;
#pragma unroll
        for (int nt = 0; nt < 8; nt++) {
            const int c = colBase + warpN * 64 + nt * 8 + (lane & 3) * 2;
            if (r0 < NN) *(float2*)&g_h1[(size_t)r0 * D1 + c] = make_float2(acc[mt][nt][0], acc[mt][nt][1]);
            if (r1 < NN) *(float2*)&g_h1[(size_t)r1 * D1 + c] = make_float2(acc[mt][nt][2], acc[mt][nt][3]);
        }
#pragma unroll
        for (int hl = 0; hl < 2; hl++) {
            float ps0 = 0.f, pd0 = 0.f, ps1 = 0.f, pd1 = 0.f;
#pragma unroll
            for (int ntq = 0; ntq < 4; ntq++) {
                const int nt = hl * 4 + ntq;
                const int c = colBase + warpN * 64 + nt * 8 + (lane & 3) * 2;
                float av0 = __ldg(&a_src1[c]), av1 = __ldg(&a_src1[c + 1]);
                float dv0 = __ldg(&a_dst1[c]), dv1 = __ldg(&a_dst1[c + 1]);
                ps0 += acc[mt][nt][0] * av0 + acc[mt][nt][1] * av1;
                pd0 += acc[mt][nt][0] * dv0 + acc[mt][nt][1] * dv1;
                ps1 += acc[mt][nt][2] * av0 + acc[mt][nt][3] * av1;
                pd1 += acc[mt][nt][2] * dv0 + acc[mt][nt][3] * dv1;
            }
#pragma unroll
            for (int off = 1; off < 4; off <<= 1) {
                ps0 += __shfl_xor_sync(0xffffffffu, ps0, off);
                pd0 += __shfl_xor_sync(0xffffffffu, pd0, off);
                ps1 += __shfl_xor_sync(0xffffffffu, ps1, off);
                pd1 += __shfl_xor_sync(0xffffffffu, pd1, off);
            }
            if ((lane & 3) == 0) {
                const int hg = (colBase >> 5) + warpN * 2 + hl;
                if (r0 < NN) { g_as1[r0 * H1 + hg] = ps0; g_ad1[r0 * H1 + hg] = pd0; }
                if (r1 < NN) { g_as1[r1 * H1 + hg] = ps1; g_ad1[r1 * H1 + hg] = pd1; }
            }
        }
    }
}

// ---------------- CSR build ---------------------------------------------------
__global__ void zero_deg_kernel() {
    int i = blockIdx.x * blockDim.x + threadIdx.x;
    if (i < NN) g_deg[i] = 0;
}

__global__ void hist_kernel(const int* __restrict__ ei) {
    int i = blockIdx.x * blockDim.x + threadIdx.x;
    if (i >= E2) return;
    int d = (i < EE) ? __ldg(&ei[EE + i]) : (i - EE);
    atomicAdd(&g_deg[d], 1);
}

__global__ void scan_block_kernel() {
    __shared__ int sh[1024];
    int tid = threadIdx.x;
    int i = blockIdx.x * 1024 + tid;
    int v = (i < NN) ? g_deg[i] : 0;
    sh[tid] = v;
    __syncthreads();
#pragma unroll
    for (int off = 1; off < 1024; off <<= 1) {
        int t = (tid >= off) ? sh[tid - off] : 0;
        __syncthreads();
        sh[tid] += t;
        __syncthreads();
    }
    if (i < NN) g_incl[i] = sh[tid];
    if (tid == 1023) g_parts[blockIdx.x] = sh[tid];
}

__global__ void scan_parts_kernel(int nb) {
    __shared__ int sh[64];
    int tid = threadIdx.x;
    int v = (tid < nb) ? g_parts[tid] : 0;
    sh[tid] = v;
    __syncthreads();
#pragma unroll
    for (int off = 1; off < 64; off <<= 1) {
        int t = (tid >= off) ? sh[tid - off] : 0;
        __syncthreads();
        sh[tid] += t;
        __syncthreads();
    }
    if (tid < nb) g_parts_ex[tid] = sh[tid] - v;
}

__global__ void finalize_scan_kernel() {
    int i = blockIdx.x * blockDim.x + threadIdx.x;
    if (i >= NN) return;
    int start = g_incl[i] - g_deg[i] + g_parts_ex[i >> 10];
    g_starts[i] = start;
    g_cursor[i] = start;
}

__global__ void fill_kernel(const int* __restrict__ ei) {
    int i = blockIdx.x * blockDim.x + threadIdx.x;
    if (i >= E2) return;
    int s, d;
    if (i < EE) { s = __ldg(&ei[i]); d = __ldg(&ei[EE + i]); }
    else        { s = i - EE; d = s; }
    int p = atomicAdd(&g_cursor[d], 1);
    g_ssrc[p] = s;
}

// ---------------- layer1 aggregation (warp per node*head) ---------------------
__global__ void agg1_kernel(const float* __restrict__ b1) {
    int gw = (blockIdx.x * blockDim.x + threadIdx.x) >> 5;
    int lane = threadIdx.x & 31;
    int n = gw >> 3;                 // node
    int h = gw & 7;                  // head
    if (n >= NN) return;
    int st = g_starts[n];
    int d  = g_deg[n];

    float adh = g_ad1[n * H1 + h];
    float* wplane = &g_wbuf[(size_t)h * E2];

    // pass A: exp per edge (coalesced plane write) + denominator
    float den = 0.f;
    for (int j = lane; j < d; j += 32) {
        int s = __ldg(&g_ssrc[st + j]);
        float e = __ldg(&g_as1[s * H1 + h]) + adh;
        e = fmaxf(e, 0.2f * e);
        float ex = __expf(e);
        wplane[st + j] = ex;
        den += ex;
    }
#pragma unroll
    for (int off = 16; off > 0; off >>= 1)
        den += __shfl_xor_sync(0xffffffffu, den, off);
    float inv = 1.f / (den + 1e-16f);

    // pass B: one aligned 128B line per edge
    float a0 = 0.f;
#pragma unroll 8
    for (int j = 0; j < d; j++) {
        int s = __ldg(&g_ssrc[st + j]);
        float w = wplane[st + j] * inv;
        a0 = fmaf(__ldg(&g_h1[(size_t)s * D1 + h * 32 + lane]), w, a0);
    }

    float v = a0 + __ldg(&b1[h * 32 + lane]);
    v = (v > 0.f) ? v : expm1f(v);
    g_hout1[(size_t)n * D1 + h * 32 + lane] = v;
}

// ---------------- layer2 linear + alpha2 --------------------------------------
__global__ void layer2_linear_kernel(const float* __restrict__ W2,
                                     const float* __restrict__ a_src2,
                                     const float* __restrict__ a_dst2) {
    __shared__ float Ws[D1 * CLS + 64];
    __shared__ float as_sh[CLS], ad_sh[CLS];
    int tid = threadIdx.x;
    for (int i = tid; i < D1 * CLS + 64; i += blockDim.x)
        Ws[i] = (i < D1 * CLS) ? W2[i] : 0.f;
    if (tid < CLS) { as_sh[tid] = a_src2[tid]; ad_sh[tid] = a_dst2[tid]; }
    __syncthreads();

    int lane = tid & 31;
    int warpsPerBlock = blockDim.x >> 5;
    int gw = blockIdx.x * warpsPerBlock + (tid >> 5);
    int stride = gridDim.x * warpsPerBlock;

    for (int n = gw; n < NN; n += stride) {
        const float* xp = &g_hout1[(size_t)n * D1];
        float acc0a = 0.f, acc0b = 0.f, acc1a = 0.f, acc1b = 0.f;
#pragma unroll
        for (int kb = 0; kb < D1 / 32; kb++) {
            float xv = xp[kb * 32 + lane];
#pragma unroll
            for (int j = 0; j < 32; j += 2) {
                float xj0 = __shfl_sync(0xffffffffu, xv, j);
                float xj1 = __shfl_sync(0xffffffffu, xv, j + 1);
                int k0 = kb * 32 + j;
                acc0a = fmaf(xj0, Ws[k0 * CLS + lane], acc0a);
                acc1a = fmaf(xj0, Ws[k0 * CLS + 32 + lane], acc1a);
                acc0b = fmaf(xj1, Ws[(k0 + 1) * CLS + lane], acc0b);
                acc1b = fmaf(xj1, Ws[(k0 + 1) * CLS + 32 + lane], acc1b);
            }
        }
        float v0 = acc0a + acc0b;
        float v1 = acc1a + acc1b;
        g_h2lin[(size_t)n * CLS + lane] = v0;
        if (lane < CLS - 32) g_h2lin[(size_t)n * CLS + 32 + lane] = v1;
        float ps = v0 * as_sh[lane] + ((lane < CLS - 32) ? v1 * as_sh[32 + lane] : 0.f);
        float pd = v0 * ad_sh[lane] + ((lane < CLS - 32) ? v1 * ad_sh[32 + lane] : 0.f);
#pragma unroll
        for (int off = 16; off > 0; off >>= 1) {
            ps += __shfl_xor_sync(0xffffffffu, ps, off);
            pd += __shfl_xor_sync(0xffffffffu, pd, off);
        }
        if (lane == 0) { g_as2[n] = ps; g_ad2[n] = pd; }
    }
}

// ---------------- layer2 aggregation + log_softmax ----------------------------
__global__ void agg2_kernel(const float* __restrict__ b2, float* __restrict__ out) {
    int n = (blockIdx.x * blockDim.x + threadIdx.x) >> 5;
    int lane = threadIdx.x & 31;
    if (n >= NN) return;
    int st = g_starts[n];
    int d  = g_deg[n];
    float adn = g_ad2[n];

    float den = 0.f;
    for (int j = lane; j < d; j += 32) {
        int s = __ldg(&g_ssrc[st + j]);
        float e = __ldg(&g_as2[s]) + adn;
        e = fmaxf(e, 0.2f * e);
        float ex = __expf(e);
        g_wbuf2[st + j] = ex;
        den += ex;
    }
#pragma unroll
    for (int off = 16; off > 0; off >>= 1)
        den += __shfl_xor_sync(0xffffffffu, den, off);
    float inv = 1.f / (den + 1e-16f);

    float acc0 = 0.f, acc1 = 0.f;
#pragma unroll 4
    for (int j = 0; j < d; j++) {
        int s = __ldg(&g_ssrc[st + j]);
        float w = g_wbuf2[st + j] * inv;
        const float* hp = &g_h2lin[(size_t)s * CLS];
        acc0 = fmaf(__ldg(&hp[lane]), w, acc0);
        if (lane < CLS - 32) acc1 = fmaf(__ldg(&hp[32 + lane]), w, acc1);
    }
    float v0 = acc0 + __ldg(&b2[lane]);
    float v1 = (lane < CLS - 32) ? (acc1 + __ldg(&b2[32 + lane])) : -CUDART_INF_F;

    float m = fmaxf(v0, v1);
#pragma unroll
    for (int off = 16; off > 0; off >>= 1)
        m = fmaxf(m, __shfl_xor_sync(0xffffffffu, m, off));
    float s0 = __expf(v0 - m) + ((lane < CLS - 32) ? __expf(v1 - m) : 0.f);
#pragma unroll
    for (int off = 16; off > 0; off >>= 1)
        s0 += __shfl_xor_sync(0xffffffffu, s0, off);
    float lse = m + logf(s0);

    out[(size_t)n * CLS + lane] = v0 - lse;
    if (lane < CLS - 32) out[(size_t)n * CLS + 32 + lane] = v1 - lse;
}

// ---------------- launch ------------------------------------------------------
extern "C" void kernel_launch(void* const* d_in, const int* in_sizes, int n_in,
                              void* d_out, int out_size) {
    const float* x      = (const float*)d_in[0];
    const int*   ei     = (const int*)d_in[1];
    const float* W1     = (const float*)d_in[2];
    const float* a_src1 = (const float*)d_in[3];
    const float* a_dst1 = (const float*)d_in[4];
    const float* b1     = (const float*)d_in[5];
    const float* W2     = (const float*)d_in[6];
    const float* a_src2 = (const float*)d_in[7];
    const float* a_dst2 = (const float*)d_in[8];
    const float* b2     = (const float*)d_in[9];
    float* out = (float*)d_out;

    const int nb_scan = (NN + 1023) / 1024;   // 49

    // prep, then GEMM at launch slot 4 (ncu capture window)
    prep_x_kernel<<<(NN * FIN / 4 + 255) / 256, 256>>>(x);
    prep_w_kernel<<<(D1 * (FIN / 2) + 255) / 256, 256>>>(W1);
    zero_deg_kernel<<<(NN + 255) / 256, 256>>>();
    sgemm1_tc_kernel<<<dim3(2, (NN + 127) / 128), 256>>>(a_src1, a_dst1);

    // CSR build chain
    hist_kernel<<<(E2 + 255) / 256, 256>>>(ei);
    scan_block_kernel<<<nb_scan, 1024>>>();
    scan_parts_kernel<<<1, 64>>>(nb_scan);
    finalize_scan_kernel<<<(NN + 255) / 256, 256>>>();
    fill_kernel<<<(E2 + 255) / 256, 256>>>(ei);

    // layer 1 aggregation (alpha1 fused into GEMM epilogue)
    agg1_kernel<<<((size_t)NN * 8 * 32 + 255) / 256, 256>>>(b1);

    // layer 2
    layer2_linear_kernel<<<592, 256>>>(W2, a_src2, a_dst2);
    agg2_kernel<<<(NN * 32 + 255) / 256, 256>>>(b2, out);
}